// round 10
// baseline (speedup 1.0000x reference)
#include <cuda_runtime.h>
#include <cuda_bf16.h>
#include <cuda_fp8.h>
#include <stdint.h>
#include <math.h>

typedef __nv_bfloat16 bf16;

#define NB   32
#define DIM  1024
#define EPSF 1e-12f

// Per-tensor fp8 scales: hi = e4m3(x * SH), lo = e4m3((x - bf16(x)) * SH*512)
#define SH_W  4096.0f
#define SL_W  2097152.0f
#define SH_X  16.0f
#define SL_X  8192.0f
#define SH_KQ 16.0f
#define SL_KQ 8192.0f
#define SH_SM 256.0f
#define SL_SM 131072.0f
// Product descale: 2^-(aA + aB + 9)
#define INVS_KQ (1.0f / 33554432.0f)   // W(12) x X(4) + 9
#define INVS_Y  (1.0f / 131072.0f)     // Q(4) x K(4) + 9
#define INVS_Z  (1.0f / 2097152.0f)    // X(4) x SM(8) + 9

// ---------------- scratch (__device__ globals; no allocations) ----------------
__device__ __align__(128) bf16    g_Wk_h [DIM*DIM];
__device__ __align__(128) uint8_t g_Wk_8h[DIM*DIM], g_Wk_8l[DIM*DIM];
__device__ __align__(128) bf16    g_Wq_h [DIM*DIM];
__device__ __align__(128) uint8_t g_Wq_8h[DIM*DIM], g_Wq_8l[DIM*DIM];
__device__ __align__(128) bf16    g_X_h  [NB*DIM*DIM];
__device__ __align__(128) uint8_t g_X_8h [NB*DIM*DIM], g_X_8l [NB*DIM*DIM];
__device__ __align__(128) bf16    g_XT_h [NB*DIM*DIM];
__device__ __align__(128) uint8_t g_XT_8h[NB*DIM*DIM], g_XT_8l[NB*DIM*DIM];
__device__ __align__(128) bf16    g_KT_h [NB*DIM*DIM];
__device__ __align__(128) uint8_t g_KT_8h[NB*DIM*DIM], g_KT_8l[NB*DIM*DIM];
__device__ __align__(128) bf16    g_QT_h [NB*DIM*DIM];
__device__ __align__(128) uint8_t g_QT_8h[NB*DIM*DIM], g_QT_8l[NB*DIM*DIM];
__device__ __align__(128) bf16    g_SM_h [NB*DIM*DIM];
__device__ __align__(128) uint8_t g_SM_8h[NB*DIM*DIM], g_SM_8l[NB*DIM*DIM];
__device__ __align__(128) float   g_YT[NB*DIM*DIM];
__device__ float g_partK[8*NB*DIM], g_partQ[8*NB*DIM];
__device__ float g_DK2[NB*DIM], g_DQ2[NB*DIM];

// ---------------- helpers ----------------
__device__ __forceinline__ uint32_t smem_to_u32(const void* p) {
    uint32_t a;
    asm("{ .reg .u64 t; cvta.to.shared.u64 t, %1; cvt.u32.u64 %0, t; }" : "=r"(a) : "l"(p));
    return a;
}
__device__ __forceinline__ uint8_t to_e4m3(float v) {
    return (uint8_t)__nv_cvt_float_to_fp8(v, __NV_SATFINITE, __NV_E4M3);
}

#define LDSM4(r, addr) \
    asm volatile("ldmatrix.sync.aligned.m8n8.x4.shared.b16 {%0,%1,%2,%3}, [%4];" \
        : "=r"((r)[0]), "=r"((r)[1]), "=r"((r)[2]), "=r"((r)[3]) : "r"(addr))

#define MMA(acc, a, b0, b1) \
    asm volatile("mma.sync.aligned.m16n8k16.row.col.f32.bf16.bf16.f32 " \
        "{%0,%1,%2,%3}, {%4,%5,%6,%7}, {%8,%9}, {%0,%1,%2,%3};" \
        : "+f"((acc)[0]), "+f"((acc)[1]), "+f"((acc)[2]), "+f"((acc)[3]) \
        : "r"((a)[0]), "r"((a)[1]), "r"((a)[2]), "r"((a)[3]), "r"(b0), "r"(b1))

#define MMA8(acc, a, b0, b1) \
    asm volatile("mma.sync.aligned.m16n8k32.row.col.f32.e4m3.e4m3.f32 " \
        "{%0,%1,%2,%3}, {%4,%5,%6,%7}, {%8,%9}, {%0,%1,%2,%3};" \
        : "+f"((acc)[0]), "+f"((acc)[1]), "+f"((acc)[2]), "+f"((acc)[3]) \
        : "r"((a)[0]), "r"((a)[1]), "r"((a)[2]), "r"((a)[3]), "r"(b0), "r"(b1))

// Stage: A{bf16 8K, e4m3h 4K, e4m3l 4K} + B(64 rows){bf16 4K, e4m3h 2K, e4m3l 2K} = 24K
#define STAGE_BYTES 24576
#define NSTAGE 3
#define SMEM_BYTES (NSTAGE * STAGE_BYTES)   // 72 KB; epilogue [128][65] f32 = 33 KB overlays

// ---------------------------------------------------------------------------
// Split GEMM: D[m,n] = sum_k A[m,k]*B[n,k], K-major operands.
// CTA 128x64, 8 warps (4m x 2n), warp tile 32x32, BK=32, 3-stage cp.async.
// Main pass bf16 hixhi -> acc; corrections Ahi8*Blo8 + Alo8*Bhi8 (e4m3,
// per-tensor scaled) -> acc8 at 2x rate; epilogue v = acc + acc8*invs.
// EPI 0: bf16 + scaled e4m3 hi/lo TRANSPOSED store out[n][m], +bias,
//        + exact deterministic per-CTA partial column norms.
// EPI 1: fp32 TRANSPOSED store, * rsqrt(max(rs[m]*cs[n], eps))
// EPI 2: fp32 direct store out[m][n]
// ---------------------------------------------------------------------------
template <int EPI>
__global__ __launch_bounds__(256, 2)
void mma_gemm(const bf16* __restrict__ Ah, const uint8_t* __restrict__ A8h,
              const uint8_t* __restrict__ A8l, size_t sA,
              const bf16* __restrict__ Bh, const uint8_t* __restrict__ B8h,
              const uint8_t* __restrict__ B8l, size_t sB,
              float* __restrict__ outF, bf16* __restrict__ oHi,
              uint8_t* __restrict__ o8h, uint8_t* __restrict__ o8l,
              const float* __restrict__ bias, const float* __restrict__ rs,
              const float* __restrict__ cs, float* __restrict__ partOut,
              float invs, float oSh, float oSl)
{
    extern __shared__ char smem[];
    const int tid  = threadIdx.x;
    const int lane = tid & 31, warp = tid >> 5;
    const int wm = (warp >> 1) * 32, wn = (warp & 1) * 32;
    const int bz = blockIdx.z;
    const int bm = blockIdx.y * 128, bn = blockIdx.x * 64;
    const uint32_t sbase = smem_to_u32(smem);

    const bf16*    pAh  = Ah  + (size_t)bz * sA + (size_t)bm * DIM;
    const uint8_t* pA8h = A8h + (size_t)bz * sA + (size_t)bm * DIM;
    const uint8_t* pA8l = A8l + (size_t)bz * sA + (size_t)bm * DIM;
    const bf16*    pBh  = Bh  + (size_t)bz * sB + (size_t)bn * DIM;
    const uint8_t* pB8h = B8h + (size_t)bz * sB + (size_t)bn * DIM;
    const uint8_t* pB8l = B8l + (size_t)bz * sB + (size_t)bn * DIM;

    // bf16 tile: rows x 64B (2 rows / 128B smem row); fp8 tile: rows x 32B (4 rows / row)
    auto load_bf16 = [&](uint32_t dst, const bf16* src, int kc, int nrow) {
        for (int j = 0; j < nrow * 4; j += 256) {
            int cid = tid + j;
            int r = cid >> 2, c = cid & 3;
            uint32_t R = (uint32_t)(r >> 1);
            uint32_t q = (uint32_t)(((r & 1) * 4 + c)) ^ (R & 7);
            asm volatile("cp.async.cg.shared.global [%0], [%1], 16;"
                         :: "r"(dst + R * 128 + q * 16),
                            "l"(src + (size_t)r * DIM + kc + c * 8));
        }
    };
    auto load_f8 = [&](uint32_t dst, const uint8_t* src, int kc, int nrow) {
        if (tid < nrow * 2) {
            int r = tid >> 1, c = tid & 1;
            uint32_t R = (uint32_t)(r >> 2);
            uint32_t q = (uint32_t)(((r & 3) * 2 + c)) ^ (R & 7);
            asm volatile("cp.async.cg.shared.global [%0], [%1], 16;"
                         :: "r"(dst + R * 128 + q * 16),
                            "l"(src + (size_t)r * DIM + kc + c * 16));
        }
    };
    auto load_stage = [&](int s, int kc) {
        uint32_t St = sbase + (uint32_t)s * STAGE_BYTES;
        load_bf16(St,          pAh,  kc, 128);
        load_f8  (St + 8192,   pA8h, kc, 128);
        load_f8  (St + 12288,  pA8l, kc, 128);
        load_bf16(St + 16384,  pBh,  kc, 64);
        load_f8  (St + 20480,  pB8h, kc, 64);
        load_f8  (St + 22528,  pB8l, kc, 64);
        asm volatile("cp.async.commit_group;" ::: "memory");
    };

    float acc [2][4][4];
    float acc8[2][4][4];
    #pragma unroll
    for (int a = 0; a < 2; a++)
        #pragma unroll
        for (int b = 0; b < 4; b++)
            #pragma unroll
            for (int c = 0; c < 4; c++) { acc[a][b][c] = 0.0f; acc8[a][b][c] = 0.0f; }

    load_stage(0, 0);
    load_stage(1, 32);

    const int NCHUNK = 32;
    for (int i = 0; i < NCHUNK; i++) {
        if (i + 1 < NCHUNK) {
            asm volatile("cp.async.wait_group 1;" ::: "memory");
        } else {
            asm volatile("cp.async.wait_group 0;" ::: "memory");
        }
        __syncthreads();
        if (i + 2 < NCHUNK) load_stage((i + 2) % NSTAGE, (i + 2) * 32);

        const uint32_t St   = sbase + (uint32_t)(i % NSTAGE) * STAGE_BYTES;
        const uint32_t Abh  = St;
        const uint32_t A8hS = St + 8192, A8lS = St + 12288;
        const uint32_t Bbh  = St + 16384;
        const uint32_t B8hS = St + 20480, B8lS = St + 22528;

        // ---- bf16 hi x hi -> acc ----
        #pragma unroll
        for (int kk = 0; kk < 2; kk++) {
            uint32_t bh[8];
            {
                const int rb = wn + ((lane >> 4) << 3) + (lane & 7);
                const uint32_t c = (uint32_t)(kk * 2 + ((lane >> 3) & 1));
                #pragma unroll
                for (int g = 0; g < 2; g++) {
                    int r = rb + g * 16;
                    uint32_t R = (uint32_t)(r >> 1);
                    uint32_t q = ((uint32_t)((r & 1) * 4) + c) ^ (R & 7);
                    LDSM4(&bh[g * 4], Bbh + R * 128 + q * 16);
                }
            }
            const int ra = wm + (lane & 15);
            const uint32_t ca = (uint32_t)(kk * 2 + (lane >> 4));
            #pragma unroll
            for (int im = 0; im < 2; im++) {
                uint32_t a[4];
                int r = ra + im * 16;
                uint32_t R = (uint32_t)(r >> 1);
                uint32_t q = ((uint32_t)((r & 1) * 4) + ca) ^ (R & 7);
                LDSM4(a, Abh + R * 128 + q * 16);
                #pragma unroll
                for (int jn = 0; jn < 4; jn++)
                    MMA(acc[im][jn], a, bh[2 * jn], bh[2 * jn + 1]);
            }
        }
        // ---- fp8 corrections -> acc8 (same net scale both passes) ----
        #pragma unroll
        for (int pass = 0; pass < 2; pass++) {
            const uint32_t Bsrc = (pass == 0) ? B8lS : B8hS;
            const uint32_t Asrc = (pass == 0) ? A8hS : A8lS;
            uint32_t bf8[8];
            {
                const int rb = wn + ((lane >> 4) << 3) + (lane & 7);
                const uint32_t c = (uint32_t)((lane >> 3) & 1);
                #pragma unroll
                for (int g = 0; g < 2; g++) {
                    int r = rb + g * 16;
                    uint32_t R = (uint32_t)(r >> 2);
                    uint32_t q = ((uint32_t)((r & 3) * 2) + c) ^ (R & 7);
                    LDSM4(&bf8[g * 4], Bsrc + R * 128 + q * 16);
                }
            }
            const int ra = wm + (lane & 15);
            const uint32_t ca = (uint32_t)(lane >> 4);
            #pragma unroll
            for (int im = 0; im < 2; im++) {
                uint32_t a[4];
                int r = ra + im * 16;
                uint32_t R = (uint32_t)(r >> 2);
                uint32_t q = ((uint32_t)((r & 3) * 2) + ca) ^ (R & 7);
                LDSM4(a, Asrc + R * 128 + q * 16);
                #pragma unroll
                for (int jn = 0; jn < 4; jn++)
                    MMA8(acc8[im][jn], a, bf8[2 * jn], bf8[2 * jn + 1]);
            }
        }
    }
    __syncthreads();

    // ---- epilogue: combine, stage through padded fp32 smem [128][65] ----
    float* sfl = (float*)smem;
    #pragma unroll
    for (int im = 0; im < 2; im++) {
        float bv0 = 0.f, bv1 = 0.f;
        if (EPI == 0) {
            bv0 = bias[bm + wm + im * 16 + (lane >> 2)];
            bv1 = bias[bm + wm + im * 16 + (lane >> 2) + 8];
        }
        #pragma unroll
        for (int jn = 0; jn < 4; jn++) {
            int m  = wm + im * 16 + (lane >> 2);
            int nn = wn + jn * 8 + 2 * (lane & 3);
            sfl[m * 65 + nn]           = acc[im][jn][0] + acc8[im][jn][0] * invs + bv0;
            sfl[m * 65 + nn + 1]       = acc[im][jn][1] + acc8[im][jn][1] * invs + bv0;
            sfl[(m + 8) * 65 + nn]     = acc[im][jn][2] + acc8[im][jn][2] * invs + bv1;
            sfl[(m + 8) * 65 + nn + 1] = acc[im][jn][3] + acc8[im][jn][3] * invs + bv1;
        }
    }
    __syncthreads();

    const size_t obase = (size_t)bz * (size_t)(DIM * DIM);
    if (EPI == 0) {
        #pragma unroll 1
        for (int idx = tid; idx < 128 * 64; idx += 256) {
            int nn = idx >> 7, m = idx & 127;
            float v = sfl[m * 65 + nn];
            bf16 h = __float2bfloat16(v);
            size_t o = obase + (size_t)(bn + nn) * DIM + bm + m;
            oHi[o] = h;
            o8h[o] = to_e4m3(v * oSh);
            o8l[o] = to_e4m3((v - __bfloat162float(h)) * oSl);
        }
        // exact deterministic partial column norms
        float* sscr = (float*)(smem + 33280);   // [4][64]
        {
            int col = tid & 63, qh = tid >> 6;
            float ps = 0.0f;
            #pragma unroll 4
            for (int m = qh * 32; m < qh * 32 + 32; m++) {
                float vv = sfl[m * 65 + col];
                ps = fmaf(vv, vv, ps);
            }
            sscr[qh * 64 + col] = ps;
        }
        __syncthreads();
        if (tid < 64)
            partOut[(size_t)(bm >> 7) * (NB * DIM) + (size_t)bz * DIM + bn + tid] =
                (sscr[tid] + sscr[64 + tid]) + (sscr[128 + tid] + sscr[192 + tid]);
    } else if (EPI == 1) {
        #pragma unroll 1
        for (int idx = tid; idx < 128 * 64; idx += 256) {
            int nn = idx >> 7, m = idx & 127;
            float v = sfl[m * 65 + nn];
            float sc = rsqrtf(fmaxf(rs[bz * DIM + bm + m] * cs[bz * DIM + bn + nn], EPSF));
            outF[obase + (size_t)(bn + nn) * DIM + bm + m] = v * sc;
        }
    } else {
        #pragma unroll 1
        for (int idx = tid; idx < 128 * 64; idx += 256) {
            int m = idx >> 6, nn = idx & 63;
            outF[obase + (size_t)(bm + m) * DIM + bn + nn] = sfl[m * 65 + nn];
        }
    }
}

// ---------------------------------------------------------------------------
// Elementwise kernels
// ---------------------------------------------------------------------------
__global__ __launch_bounds__(256)
void w_split(const float* __restrict__ Wk, const float* __restrict__ Wq)
{
    int i = blockIdx.x * 256 + threadIdx.x;
    float a = Wk[i];
    bf16 h = __float2bfloat16(a);
    g_Wk_h[i] = h; g_Wk_8h[i] = to_e4m3(a * SH_W);
    g_Wk_8l[i] = to_e4m3((a - __bfloat162float(h)) * SL_W);
    float b = Wq[i];
    h = __float2bfloat16(b);
    g_Wq_h[i] = h; g_Wq_8h[i] = to_e4m3(b * SH_W);
    g_Wq_8l[i] = to_e4m3((b - __bfloat162float(h)) * SL_W);
}

__global__ __launch_bounds__(256)
void xprep(const float* __restrict__ X)
{
    __shared__ float t[32][33];
    const int n = blockIdx.z, b0 = blockIdx.x * 32, d0 = blockIdx.y * 32;
    const int tx = threadIdx.x, ty = threadIdx.y;
    const size_t base = (size_t)n << 20;
    const float* Xn = X + base;
    #pragma unroll
    for (int r = 0; r < 4; r++) {
        int row = ty + r * 8;
        float v = Xn[(size_t)(d0 + row) * DIM + b0 + tx];
        t[row][tx] = v;
        bf16 h = __float2bfloat16(v);
        size_t o = base + (size_t)(d0 + row) * DIM + b0 + tx;
        g_X_h[o] = h; g_X_8h[o] = to_e4m3(v * SH_X);
        g_X_8l[o] = to_e4m3((v - __bfloat162float(h)) * SL_X);
    }
    __syncthreads();
    #pragma unroll
    for (int r = 0; r < 4; r++) {
        int row = ty + r * 8;
        float v = t[tx][row];
        bf16 h = __float2bfloat16(v);
        size_t o = base + (size_t)(b0 + row) * DIM + d0 + tx;
        g_XT_h[o] = h; g_XT_8h[o] = to_e4m3(v * SH_X);
        g_XT_8l[o] = to_e4m3((v - __bfloat162float(h)) * SL_X);
    }
}

__global__ __launch_bounds__(256)
void norms_red()
{
    int idx = blockIdx.x * 256 + threadIdx.x;
    float sk = 0.f, sq = 0.f;
    #pragma unroll
    for (int t = 0; t < 8; t++) {
        sk += g_partK[t * (NB * DIM) + idx];
        sq += g_partQ[t * (NB * DIM) + idx];
    }
    g_DK2[idx] = sk;
    g_DQ2[idx] = sq;
}

__global__ __launch_bounds__(256)
void softmax_k()
{
    const int row = blockIdx.x;
    const int tid = threadIdx.x;
    float* y = g_YT + ((size_t)row << 10);
    float v[4];
    #pragma unroll
    for (int j = 0; j < 4; j++) v[j] = y[tid + j * 256];
    float m = fmaxf(fmaxf(v[0], v[1]), fmaxf(v[2], v[3]));
    __shared__ float red[8];
    #pragma unroll
    for (int o = 16; o > 0; o >>= 1) m = fmaxf(m, __shfl_xor_sync(0xFFFFFFFFu, m, o));
    if ((tid & 31) == 0) red[tid >> 5] = m;
    __syncthreads();
    float mall = red[0];
    #pragma unroll
    for (int w = 1; w < 8; w++) mall = fmaxf(mall, red[w]);
    float s = 0.f;
    #pragma unroll
    for (int j = 0; j < 4; j++) { v[j] = __expf(v[j] - mall); s += v[j]; }
    #pragma unroll
    for (int o = 16; o > 0; o >>= 1) s += __shfl_xor_sync(0xFFFFFFFFu, s, o);
    __syncthreads();
    if ((tid & 31) == 0) red[tid >> 5] = s;
    __syncthreads();
    float st = 0.f;
    #pragma unroll
    for (int w = 0; w < 8; w++) st += red[w];
    const float inv = 1.0f / st;
    #pragma unroll
    for (int j = 0; j < 4; j++) {
        float p = v[j] * inv;
        bf16 h = __float2bfloat16(p);
        size_t o = ((size_t)row << 10) + tid + j * 256;
        g_SM_h[o] = h; g_SM_8h[o] = to_e4m3(p * SH_SM);
        g_SM_8l[o] = to_e4m3((p - __bfloat162float(h)) * SL_SM);
    }
}

// ---------------------------------------------------------------------------
extern "C" void kernel_launch(void* const* d_in, const int* in_sizes, int n_in,
                              void* d_out, int out_size)
{
    const float* X   = (const float*)d_in[0];
    const float* Wk  = (const float*)d_in[1];
    const float* Wq  = (const float*)d_in[2];
    const float* Wk0 = (const float*)d_in[3];
    const float* Wq0 = (const float*)d_in[4];
    float* Z = (float*)d_out;

    cudaFuncSetAttribute(mma_gemm<0>, cudaFuncAttributeMaxDynamicSharedMemorySize, SMEM_BYTES);
    cudaFuncSetAttribute(mma_gemm<1>, cudaFuncAttributeMaxDynamicSharedMemorySize, SMEM_BYTES);
    cudaFuncSetAttribute(mma_gemm<2>, cudaFuncAttributeMaxDynamicSharedMemorySize, SMEM_BYTES);

    bf16 *Wkh, *Wqh, *Xh, *XTh, *KTh, *QTh, *SMh;
    uint8_t *Wk8h, *Wk8l, *Wq8h, *Wq8l, *X8h, *X8l, *XT8h, *XT8l;
    uint8_t *KT8h, *KT8l, *QT8h, *QT8l, *SM8h, *SM8l;
    float *YT, *dk2, *dq2, *pK, *pQ;
    cudaGetSymbolAddress((void**)&Wkh,  g_Wk_h);   cudaGetSymbolAddress((void**)&Wk8h, g_Wk_8h);
    cudaGetSymbolAddress((void**)&Wk8l, g_Wk_8l);
    cudaGetSymbolAddress((void**)&Wqh,  g_Wq_h);   cudaGetSymbolAddress((void**)&Wq8h, g_Wq_8h);
    cudaGetSymbolAddress((void**)&Wq8l, g_Wq_8l);
    cudaGetSymbolAddress((void**)&Xh,   g_X_h);    cudaGetSymbolAddress((void**)&X8h,  g_X_8h);
    cudaGetSymbolAddress((void**)&X8l,  g_X_8l);
    cudaGetSymbolAddress((void**)&XTh,  g_XT_h);   cudaGetSymbolAddress((void**)&XT8h, g_XT_8h);
    cudaGetSymbolAddress((void**)&XT8l, g_XT_8l);
    cudaGetSymbolAddress((void**)&KTh,  g_KT_h);   cudaGetSymbolAddress((void**)&KT8h, g_KT_8h);
    cudaGetSymbolAddress((void**)&KT8l, g_KT_8l);
    cudaGetSymbolAddress((void**)&QTh,  g_QT_h);   cudaGetSymbolAddress((void**)&QT8h, g_QT_8h);
    cudaGetSymbolAddress((void**)&QT8l, g_QT_8l);
    cudaGetSymbolAddress((void**)&SMh,  g_SM_h);   cudaGetSymbolAddress((void**)&SM8h, g_SM_8h);
    cudaGetSymbolAddress((void**)&SM8l, g_SM_8l);
    cudaGetSymbolAddress((void**)&YT,   g_YT);
    cudaGetSymbolAddress((void**)&dk2,  g_DK2);    cudaGetSymbolAddress((void**)&dq2,  g_DQ2);
    cudaGetSymbolAddress((void**)&pK,   g_partK);  cudaGetSymbolAddress((void**)&pQ,   g_partQ);

    const size_t S = (size_t)DIM * DIM;
    dim3 gg(16, 8, NB);   // n-tiles 64, m-tiles 128

    w_split<<<(DIM * DIM) / 256, 256>>>(Wk, Wq);
    xprep<<<dim3(32, 32, NB), dim3(32, 8)>>>(X);

    // KT = (Wk @ X)^T + Wk0 ; QT likewise; fused exact partial norms
    mma_gemm<0><<<gg, 256, SMEM_BYTES>>>(Wkh, Wk8h, Wk8l, 0, XTh, XT8h, XT8l, S,
                                         nullptr, KTh, KT8h, KT8l, Wk0, nullptr, nullptr, pK,
                                         INVS_KQ, SH_KQ, SL_KQ);
    mma_gemm<0><<<gg, 256, SMEM_BYTES>>>(Wqh, Wq8h, Wq8l, 0, XTh, XT8h, XT8l, S,
                                         nullptr, QTh, QT8h, QT8l, Wq0, nullptr, nullptr, pQ,
                                         INVS_KQ, SH_KQ, SL_KQ);
    norms_red<<<(NB * DIM) / 256, 256>>>();

    // YT[k,q] = (Q^T K)[q,k] * rsqrt(max(DQ2[q]*DK2[k], eps))
    mma_gemm<1><<<gg, 256, SMEM_BYTES>>>(QTh, QT8h, QT8l, S, KTh, KT8h, KT8l, S,
                                         YT, nullptr, nullptr, nullptr, nullptr, dq2, dk2, nullptr,
                                         INVS_Y, 0.f, 0.f);
    softmax_k<<<NB * DIM, 256>>>();

    // Z = X @ SM
    mma_gemm<2><<<gg, 256, SMEM_BYTES>>>(Xh, X8h, X8l, S, SMh, SM8h, SM8l, S,
                                         Z, nullptr, nullptr, nullptr, nullptr, nullptr, nullptr, nullptr,
                                         INVS_Z, 0.f, 0.f);
}